// round 12
// baseline (speedup 1.0000x reference)
#include <cuda_runtime.h>

// Leapfrog integrator, softened central potential:
//   accel(q) = -q / (r*(r+1)^2 + 1e-12)
//
// R9: chain-latency attack (we are latency-bound: total independent chains
// per SMSP is fixed at ~3.5 by problem size, so serial chain length per step
// sets the floor).
//  - sqrt.approx(S) replaces rsqrt(S)*S: removes a dependent mul (-4cy).
//  - Per-lane scalar denominator + UNCOUPLED rcp per lane (R8's batched rcp
//    coupled the lanes and regressed; this keeps lanes independent).
//    s+1 and 2s+eps compute off-chain during the SQRT latency.
//  - STEP2 macro manually interleaves the two independent particle-pair
//    chains so chain B's FMAs fill chain A's MUFU shadows.
// Layout: 2 particle-pairs (4 bodies) per thread, f32x2 state, 32768 threads,
// 1024 uniform blocks of 32 (6.92 blocks/SM, balanced).
//
// Inputs: d_in[0]=ts f32[N], d_in[1]=w0_lead f32[N,6], d_in[2]=w0_trail f32[N,6],
//         d_in[3]=n_steps i32[1]
// Output: f32[2N,6], row 2i = trail_i, row 2i+1 = lead_i.

typedef unsigned long long u64;

__device__ __forceinline__ u64 pk(float lo, float hi) {
    u64 r; asm("mov.b64 %0, {%1,%2};" : "=l"(r) : "f"(lo), "f"(hi)); return r;
}
__device__ __forceinline__ void upk(u64 v, float& lo, float& hi) {
    asm("mov.b64 {%0,%1}, %2;" : "=f"(lo), "=f"(hi) : "l"(v));
}
__device__ __forceinline__ u64 fma2(u64 a, u64 b, u64 c) {
    u64 d; asm("fma.rn.f32x2 %0, %1, %2, %3;" : "=l"(d) : "l"(a), "l"(b), "l"(c)); return d;
}
__device__ __forceinline__ u64 mul2(u64 a, u64 b) {
    u64 d; asm("mul.rn.f32x2 %0, %1, %2;" : "=l"(d) : "l"(a), "l"(b)); return d;
}
__device__ __forceinline__ float fsqrt_fast(float x) {
    float r; asm("sqrt.approx.f32 %0, %1;" : "=f"(r) : "f"(x)); return r;
}
__device__ __forceinline__ float frcp_fast(float x) {
    float r; asm("rcp.approx.f32 %0, %1;" : "=f"(r) : "f"(x)); return r;
}

// One fused step for BOTH pairs, manually interleaved:
// drift; S = |q|^2; r = sqrt(S); d = r*(S+1) + (2S+eps); cd = dtn/d; kick.
#define STEP2()                                                        \
    do {                                                               \
        XA = fma2(DT2A, PXA, XA);  XB = fma2(DT2B, PXB, XB);           \
        YA = fma2(DT2A, PYA, YA);  YB = fma2(DT2B, PYB, YB);           \
        ZA = fma2(DT2A, PZA, ZA);  ZB = fma2(DT2B, PZB, ZB);           \
        u64 SA_ = mul2(XA, XA);    u64 SB_ = mul2(XB, XB);             \
        SA_ = fma2(YA, YA, SA_);   SB_ = fma2(YB, YB, SB_);            \
        SA_ = fma2(ZA, ZA, SA_);   SB_ = fma2(ZB, ZB, SB_);            \
        float sa0, sa1, sb0, sb1;                                      \
        upk(SA_, sa0, sa1);        upk(SB_, sb0, sb1);                 \
        float ra0 = fsqrt_fast(sa0), ra1 = fsqrt_fast(sa1);            \
        float rb0 = fsqrt_fast(sb0), rb1 = fsqrt_fast(sb1);            \
        float wa0 = fmaf(2.0f, sa0, 1e-12f), wa1 = fmaf(2.0f, sa1, 1e-12f); \
        float wb0 = fmaf(2.0f, sb0, 1e-12f), wb1 = fmaf(2.0f, sb1, 1e-12f); \
        float da0 = fmaf(ra0, sa0 + 1.0f, wa0);                        \
        float da1 = fmaf(ra1, sa1 + 1.0f, wa1);                        \
        float db0 = fmaf(rb0, sb0 + 1.0f, wb0);                        \
        float db1 = fmaf(rb1, sb1 + 1.0f, wb1);                        \
        float ca0 = frcp_fast(da0), ca1 = frcp_fast(da1);              \
        float cb0 = frcp_fast(db0), cb1 = frcp_fast(db1);              \
        u64 CDA_ = pk(dtnA * ca0, dtnA * ca1);                         \
        u64 CDB_ = pk(dtnB * cb0, dtnB * cb1);                         \
        CDA = CDA_; CDB = CDB_;                                        \
        PXA = fma2(CDA_, XA, PXA); PXB = fma2(CDB_, XB, PXB);          \
        PYA = fma2(CDA_, YA, PYA); PYB = fma2(CDB_, YB, PYB);          \
        PZA = fma2(CDA_, ZA, PZA); PZB = fma2(CDB_, ZB, PZB);          \
    } while (0)

__global__ void __launch_bounds__(32)
leapfrog9_kernel(const float* __restrict__ ts,
                 const float* __restrict__ w_lead,
                 const float* __restrict__ w_trail,
                 const int* __restrict__ n_steps_p,
                 float* __restrict__ out,
                 int n) {
    int idx  = blockIdx.x * 32 + threadIdx.x;
    int half = (n + 1) >> 1;
    if (idx >= half) return;

    const int iA = idx;
    const int iB = idx + half;
    const bool hasB = (iB < n);
    const int iBc = hasB ? iB : iA;

    const int nst = *n_steps_p;
    const float t_f = ts[n - 1] + 0.001f;

    const u64 NH2 = pk(-0.5f, -0.5f);

    // ---- load pair A (lead lo, trail hi) ----
    float dtA  = (t_f - ts[iA]) / (float)nst;
    float dtnA = -dtA;
    const float2* lpA = reinterpret_cast<const float2*>(w_lead  + 6 * (size_t)iA);
    const float2* tpA = reinterpret_cast<const float2*>(w_trail + 6 * (size_t)iA);
    float2 a0 = lpA[0], a1 = lpA[1], a2 = lpA[2];
    float2 b0 = tpA[0], b1 = tpA[1], b2 = tpA[2];
    u64 XA  = pk(a0.x, b0.x), YA  = pk(a0.y, b0.y), ZA  = pk(a1.x, b1.x);
    u64 PXA = pk(a1.y, b1.y), PYA = pk(a2.x, b2.x), PZA = pk(a2.y, b2.y);
    const u64 DT2A = pk(dtA, dtA);

    // ---- load pair B ----
    float dtB  = (t_f - ts[iBc]) / (float)nst;
    float dtnB = -dtB;
    const float2* lpB = reinterpret_cast<const float2*>(w_lead  + 6 * (size_t)iBc);
    const float2* tpB = reinterpret_cast<const float2*>(w_trail + 6 * (size_t)iBc);
    float2 c0 = lpB[0], c1 = lpB[1], c2 = lpB[2];
    float2 d0v = tpB[0], d1v = tpB[1], d2v = tpB[2];
    u64 XB  = pk(c0.x, d0v.x), YB  = pk(c0.y, d0v.y), ZB  = pk(c1.x, d1v.x);
    u64 PXB = pk(c1.y, d1v.y), PYB = pk(c2.x, d2v.x), PZB = pk(c2.y, d2v.y);
    const u64 DT2B = pk(dtB, dtB);

    u64 CDA, CDB;

    // ---- pre-kick: p += h*a(q0) -> p = fma(CD, q, p), CD = -h*c ----
    {
        float hnA = -0.5f * dtA, hnB = -0.5f * dtB;
        float sa0, sa1, sb0, sb1;
        u64 SA_ = mul2(XA, XA); SA_ = fma2(YA, YA, SA_); SA_ = fma2(ZA, ZA, SA_);
        u64 SB_ = mul2(XB, XB); SB_ = fma2(YB, YB, SB_); SB_ = fma2(ZB, ZB, SB_);
        upk(SA_, sa0, sa1); upk(SB_, sb0, sb1);
        float ra0 = fsqrt_fast(sa0), ra1 = fsqrt_fast(sa1);
        float rb0 = fsqrt_fast(sb0), rb1 = fsqrt_fast(sb1);
        float da0 = fmaf(ra0, sa0 + 1.0f, fmaf(2.0f, sa0, 1e-12f));
        float da1 = fmaf(ra1, sa1 + 1.0f, fmaf(2.0f, sa1, 1e-12f));
        float db0 = fmaf(rb0, sb0 + 1.0f, fmaf(2.0f, sb0, 1e-12f));
        float db1 = fmaf(rb1, sb1 + 1.0f, fmaf(2.0f, sb1, 1e-12f));
        u64 KA = pk(hnA * frcp_fast(da0), hnA * frcp_fast(da1));
        u64 KB = pk(hnB * frcp_fast(db0), hnB * frcp_fast(db1));
        PXA = fma2(KA, XA, PXA); PYA = fma2(KA, YA, PYA); PZA = fma2(KA, ZA, PZA);
        PXB = fma2(KB, XB, PXB); PYB = fma2(KB, YB, PYB); PZB = fma2(KB, ZB, PZB);
    }

    if (nst == 64) {
#pragma unroll 8
        for (int s = 0; s < 64; s++) STEP2();
    } else {
#pragma unroll 2
        for (int s = 0; s < nst; s++) STEP2();
    }

    // post-correction: loop applied full-dt kick at last accel; restore half:
    // p += h*a_last = fma(-0.5*CD, q, p)   (CD = -dt*c)
    {
        u64 KA = mul2(CDA, NH2);
        u64 KB = mul2(CDB, NH2);
        PXA = fma2(KA, XA, PXA); PYA = fma2(KA, YA, PYA); PZA = fma2(KA, ZA, PZA);
        PXB = fma2(KB, XB, PXB); PYB = fma2(KB, YB, PYB); PZB = fma2(KB, ZB, PZB);
    }

    // ---- store: rows 2i (trail) / 2i+1 (lead) = 48 contiguous 16B-aligned bytes
    {
        float qxl, qxt, qyl, qyt, qzl, qzt, pxl, pxt, pyl, pyt, pzl, pzt;
        upk(XA, qxl, qxt);  upk(YA, qyl, qyt);  upk(ZA, qzl, qzt);
        upk(PXA, pxl, pxt); upk(PYA, pyl, pyt); upk(PZA, pzl, pzt);
        float4* op = reinterpret_cast<float4*>(out + 12 * (size_t)iA);
        op[0] = make_float4(qxt, qyt, qzt, pxt);
        op[1] = make_float4(pyt, pzt, qxl, qyl);
        op[2] = make_float4(qzl, pxl, pyl, pzl);
    }
    if (hasB) {
        float qxl, qxt, qyl, qyt, qzl, qzt, pxl, pxt, pyl, pyt, pzl, pzt;
        upk(XB, qxl, qxt);  upk(YB, qyl, qyt);  upk(ZB, qzl, qzt);
        upk(PXB, pxl, pxt); upk(PYB, pyl, pyt); upk(PZB, pzl, pzt);
        float4* op = reinterpret_cast<float4*>(out + 12 * (size_t)iB);
        op[0] = make_float4(qxt, qyt, qzt, pxt);
        op[1] = make_float4(pyt, pzt, qxl, qyl);
        op[2] = make_float4(qzl, pxl, pyl, pzl);
    }
}

extern "C" void kernel_launch(void* const* d_in, const int* in_sizes, int n_in,
                              void* d_out, int out_size) {
    const float* ts      = (const float*)d_in[0];
    const float* w_lead  = (const float*)d_in[1];
    const float* w_trail = (const float*)d_in[2];
    const int*   n_steps = (const int*)d_in[3];
    float* out = (float*)d_out;

    int n = in_sizes[0];
    int half = (n + 1) / 2;
    int block = 32;
    int grid = (half + block - 1) / block;  // 1024 blocks @ N=65536
    leapfrog9_kernel<<<grid, block>>>(ts, w_lead, w_trail, n_steps, out, n);
}